// round 1
// baseline (speedup 1.0000x reference)
#include <cuda_runtime.h>

// Problem dims (static for this problem instance)
#define B_DIM 8
#define C_DIM 256
#define L_DIM 2048
#define K_CB  8192
#define M_DIM (B_DIM * L_DIM)           // 16384 rows (b,l)
#define EMB_N (B_DIM * C_DIM * L_DIM)   // 4194304 emb elements

// GEMM-argmax tiling
#define BM 64
#define BN 128
#define BK 16

// Scratch (no allocation allowed in kernel_launch)
__device__ float g_csq[K_CB];
__device__ int   g_code[M_DIM];
__device__ float g_partial[EMB_N / 256];

// ---------------- packed f32x2 helpers (Blackwell 2x fp32 rate) -------------
__device__ __forceinline__ unsigned long long fma2(unsigned long long a,
                                                   unsigned long long b,
                                                   unsigned long long c) {
    unsigned long long d;
    asm("fma.rn.f32x2 %0, %1, %2, %3;" : "=l"(d) : "l"(a), "l"(b), "l"(c));
    return d;
}
__device__ __forceinline__ unsigned long long dup2(float v) {
    unsigned long long d;
    unsigned u = __float_as_uint(v);
    asm("mov.b64 %0, {%1, %1};" : "=l"(d) : "r"(u));
    return d;
}

// ---------------- kernel 1: codebook squared norms ---------------------------
__global__ void csq_kernel(const float* __restrict__ cb) {
    int k = blockIdx.x * 8 + (threadIdx.x >> 5);
    int lane = threadIdx.x & 31;
    const float* row = cb + (size_t)k * C_DIM;
    float s = 0.0f;
    #pragma unroll
    for (int c = lane; c < C_DIM; c += 32) { float v = row[c]; s = fmaf(v, v, s); }
    #pragma unroll
    for (int o = 16; o > 0; o >>= 1) s += __shfl_xor_sync(0xffffffffu, s, o);
    if (lane == 0) g_csq[k] = s;
}

// ---------------- kernel 2: fused GEMM + row argmax ---------------------------
// score(row, k) = ||c_k||^2 - 2 * dot(x_row, c_k)   (maximize; ties -> lowest k)
__global__ __launch_bounds__(256) void argmax_kernel(const float* __restrict__ x,
                                                     const float* __restrict__ cb) {
    __shared__ __align__(16) float As[BK][BM];
    __shared__ __align__(16) float Bs[BK][BN];
    __shared__ float csqS[BN];
    __shared__ float redV[BM][16];
    __shared__ int   redI[BM][16];
    __shared__ float bestV[BM];
    __shared__ int   bestI[BM];

    const int tid = threadIdx.x;
    const int tx = tid & 15;    // column group (8 codewords each)
    const int ty = tid >> 4;    // row group (4 rows each)

    const int rowBase = blockIdx.x * BM;
    const int b  = rowBase / L_DIM;
    const int l0 = rowBase % L_DIM;          // BM=64 divides L: block stays in one b
    const float* xb = x + (size_t)b * C_DIM * L_DIM + l0;

    if (tid < BM) { bestV[tid] = -3.0e38f; bestI[tid] = 0; }

    // A tile load mapping: k row = tid>>4 (0..15), m = (tid&15)*4 (float4 along l)
    const int a_k = tid >> 4;
    const int a_m = (tid & 15) * 4;
    // B tile load mapping: n = tid&127, c offset half = (tid>>7)*8
    const int b_n  = tid & 127;
    const int b_c0 = (tid >> 7) * 8;

    for (int kt = 0; kt < K_CB / BN; ++kt) {
        if (tid < BN) csqS[tid] = g_csq[kt * BN + tid];

        unsigned long long acc[4][4];
        #pragma unroll
        for (int i = 0; i < 4; ++i)
            #pragma unroll
            for (int p = 0; p < 4; ++p) acc[i][p] = 0ULL;

        const float* cbt = cb + (size_t)kt * BN * C_DIM;

        for (int ck = 0; ck < C_DIM; ck += BK) {
            // load A tile: As[k][m] = x[b, ck+k, l0+m]  (coalesced along l)
            float4 av = *(const float4*)(xb + (size_t)(ck + a_k) * L_DIM + a_m);
            *(float4*)&As[a_k][a_m] = av;
            // load B tile: Bs[c][n] = codebook[kt*BN+n, ck+c]
            const float* bp = cbt + (size_t)b_n * C_DIM + ck + b_c0;
            float4 bv0 = *(const float4*)(bp);
            float4 bv1 = *(const float4*)(bp + 4);
            Bs[b_c0 + 0][b_n] = bv0.x;
            Bs[b_c0 + 1][b_n] = bv0.y;
            Bs[b_c0 + 2][b_n] = bv0.z;
            Bs[b_c0 + 3][b_n] = bv0.w;
            Bs[b_c0 + 4][b_n] = bv1.x;
            Bs[b_c0 + 5][b_n] = bv1.y;
            Bs[b_c0 + 6][b_n] = bv1.z;
            Bs[b_c0 + 7][b_n] = bv1.w;
            __syncthreads();

            #pragma unroll
            for (int k = 0; k < BK; ++k) {
                float4 a4 = *(const float4*)&As[k][ty * 4];
                unsigned long long aa0 = dup2(a4.x);
                unsigned long long aa1 = dup2(a4.y);
                unsigned long long aa2 = dup2(a4.z);
                unsigned long long aa3 = dup2(a4.w);
                const unsigned long long* brow =
                    (const unsigned long long*)&Bs[k][tx * 8];
                unsigned long long b0 = brow[0], b1 = brow[1],
                                   b2 = brow[2], b3 = brow[3];
                acc[0][0] = fma2(aa0, b0, acc[0][0]);
                acc[0][1] = fma2(aa0, b1, acc[0][1]);
                acc[0][2] = fma2(aa0, b2, acc[0][2]);
                acc[0][3] = fma2(aa0, b3, acc[0][3]);
                acc[1][0] = fma2(aa1, b0, acc[1][0]);
                acc[1][1] = fma2(aa1, b1, acc[1][1]);
                acc[1][2] = fma2(aa1, b2, acc[1][2]);
                acc[1][3] = fma2(aa1, b3, acc[1][3]);
                acc[2][0] = fma2(aa2, b0, acc[2][0]);
                acc[2][1] = fma2(aa2, b1, acc[2][1]);
                acc[2][2] = fma2(aa2, b2, acc[2][2]);
                acc[2][3] = fma2(aa2, b3, acc[2][3]);
                acc[3][0] = fma2(aa3, b0, acc[3][0]);
                acc[3][1] = fma2(aa3, b1, acc[3][1]);
                acc[3][2] = fma2(aa3, b2, acc[3][2]);
                acc[3][3] = fma2(aa3, b3, acc[3][3]);
            }
            __syncthreads();
        }

        // per-thread reduce over its 8 columns (ascending n for tie-break)
        #pragma unroll
        for (int i = 0; i < 4; ++i) {
            int row = ty * 4 + i;
            float bv = -3.0e38f; int bi = 0;
            #pragma unroll
            for (int p = 0; p < 4; ++p) {
                unsigned long long a = acc[i][p];
                float dlo = __uint_as_float((unsigned)(a & 0xffffffffu));
                float dhi = __uint_as_float((unsigned)(a >> 32));
                int n0 = tx * 8 + 2 * p;
                float s0 = csqS[n0]     - 2.0f * dlo;
                float s1 = csqS[n0 + 1] - 2.0f * dhi;
                if (s0 > bv) { bv = s0; bi = n0; }
                if (s1 > bv) { bv = s1; bi = n0 + 1; }
            }
            redV[row][tx] = bv;
            redI[row][tx] = kt * BN + bi;
        }
        __syncthreads();

        if (tid < BM) {
            float bv = bestV[tid]; int bi = bestI[tid];
            #pragma unroll
            for (int t = 0; t < 16; ++t) {
                float v = redV[tid][t];
                if (v > bv) { bv = v; bi = redI[tid][t]; }
            }
            bestV[tid] = bv; bestI[tid] = bi;
        }
        __syncthreads();
    }

    if (tid < BM) g_code[rowBase + tid] = bestI[tid];
}

// ---------------- kernel 3: code -> float output -----------------------------
__global__ void code_cast_kernel(float* __restrict__ out_code) {
    int i = blockIdx.x * 256 + threadIdx.x;
    if (i < M_DIM) out_code[i] = (float)g_code[i];
}

// ---------------- kernel 4: gather emb (B,C,L) + per-block loss partials -----
__global__ void gather_loss_kernel(const float* __restrict__ x,
                                   const float* __restrict__ cb,
                                   float* __restrict__ emb_out) {
    __shared__ float sred[256];
    int idx = blockIdx.x * 256 + threadIdx.x;     // < EMB_N
    int bb  = idx >> 19;                           // / (C*L) = / 524288
    int rem = idx & ((1 << 19) - 1);
    int c   = rem >> 11;                           // / L
    int l   = rem & (L_DIM - 1);
    int code = g_code[bb * L_DIM + l];
    float v = __ldg(&cb[(size_t)code * C_DIM + c]);
    emb_out[idx] = v;
    float d = x[idx] - v;
    sred[threadIdx.x] = d * d;
    __syncthreads();
    #pragma unroll
    for (int o = 128; o > 0; o >>= 1) {
        if (threadIdx.x < o) sred[threadIdx.x] += sred[threadIdx.x + o];
        __syncthreads();
    }
    if (threadIdx.x == 0) g_partial[blockIdx.x] = sred[0];
}

// ---------------- kernel 5: deterministic final loss reduction ---------------
__global__ void finalize_kernel(float* __restrict__ loss_out) {
    __shared__ float sred[256];
    float s = 0.0f;
    for (int i = threadIdx.x; i < EMB_N / 256; i += 256) s += g_partial[i];
    sred[threadIdx.x] = s;
    __syncthreads();
    #pragma unroll
    for (int o = 128; o > 0; o >>= 1) {
        if (threadIdx.x < o) sred[threadIdx.x] += sred[threadIdx.x + o];
        __syncthreads();
    }
    if (threadIdx.x == 0) loss_out[0] = sred[0] * (1.0f / (float)EMB_N);
}

// ---------------- launch ------------------------------------------------------
extern "C" void kernel_launch(void* const* d_in, const int* in_sizes, int n_in,
                              void* d_out, int out_size) {
    const float* x  = (const float*)d_in[0];   // (8, 256, 2048)
    const float* cb = (const float*)d_in[1];   // (8192, 256)
    float* out = (float*)d_out;

    csq_kernel<<<K_CB / 8, 256>>>(cb);
    argmax_kernel<<<M_DIM / BM, 256>>>(x, cb);

    const int full = M_DIM + EMB_N + 1;
    if (out_size >= full) {
        // layout: [code (16384), emb (4194304), loss (1)] in return order
        code_cast_kernel<<<(M_DIM + 255) / 256, 256>>>(out);
        gather_loss_kernel<<<EMB_N / 256, 256>>>(x, cb, out + M_DIM);
        finalize_kernel<<<1, 256>>>(out + M_DIM + EMB_N);
    } else if (out_size == EMB_N) {
        gather_loss_kernel<<<EMB_N / 256, 256>>>(x, cb, out);
    } else if (out_size == M_DIM) {
        code_cast_kernel<<<(M_DIM + 255) / 256, 256>>>(out);
    } else {
        // unknown layout: best effort — emb first
        gather_loss_kernel<<<EMB_N / 256, 256>>>(x, cb, out);
    }
}

// round 2
// speedup vs baseline: 1.4728x; 1.4728x over previous
#include <cuda_runtime.h>

typedef unsigned long long ULL;

// Problem dims (static for this problem instance)
#define B_DIM 8
#define C_DIM 256
#define L_DIM 2048
#define K_CB  8192
#define M_DIM (B_DIM * L_DIM)           // 16384 rows (b,l)
#define EMB_N (B_DIM * C_DIM * L_DIM)   // 4194304 emb elements

// GEMM-argmax tiling
#define BM 64
#define BN 128
#define BK 32
#define NSPLIT 8                         // codebook splits (1024 words each)
#define KT_PER_SPLIT ((K_CB / BN) / NSPLIT)   // 8 tiles of 128

#define AS_STRIDE 132                    // 128 duplicated floats + 4 pad
#define AS_BUF (BK * AS_STRIDE)          // floats per A buffer
#define BS_BUF (BK * BN)                 // floats per B buffer
#define SMEM_FLOATS (2 * AS_BUF + 2 * BS_BUF)
#define SMEM_BYTES (SMEM_FLOATS * 4)

// Scratch (no allocation allowed in kernel_launch)
__device__ float g_csq[K_CB];
__device__ int   g_code[M_DIM];
__device__ ULL   g_part[M_DIM * NSPLIT];
__device__ float g_partial[EMB_N / 256];

// ---------------- packed f32x2 helpers (Blackwell 2x fp32 rate) -------------
__device__ __forceinline__ ULL fma2(ULL a, ULL b, ULL c) {
    ULL d;
    asm("fma.rn.f32x2 %0, %1, %2, %3;" : "=l"(d) : "l"(a), "l"(b), "l"(c));
    return d;
}

// monotone order-preserving key: larger score -> larger key; ties -> lower idx wins
__device__ __forceinline__ ULL makeKey(float s, int gk) {
    unsigned u = __float_as_uint(s);
    u = (u & 0x80000000u) ? ~u : (u | 0x80000000u);
    return ((ULL)u << 32) | (unsigned)(0xFFFFFFFFu - (unsigned)gk);
}
__device__ __forceinline__ ULL maxk(ULL a, ULL b) { return a > b ? a : b; }

// ---------------- kernel 1: codebook squared norms ---------------------------
__global__ void csq_kernel(const float* __restrict__ cb) {
    int k = blockIdx.x * 8 + (threadIdx.x >> 5);
    int lane = threadIdx.x & 31;
    const float* row = cb + (size_t)k * C_DIM;
    float s = 0.0f;
    #pragma unroll
    for (int c = lane; c < C_DIM; c += 32) { float v = row[c]; s = fmaf(v, v, s); }
    #pragma unroll
    for (int o = 16; o > 0; o >>= 1) s += __shfl_xor_sync(0xffffffffu, s, o);
    if (lane == 0) g_csq[k] = s;
}

// ---------------- kernel 2: fused GEMM + row argmax (split-K over codebook) --
// score(row, k) = ||c_k||^2 - 2 * dot(x_row, c_k)   (maximize; ties -> lowest k)
__global__ __launch_bounds__(256, 2) void argmax_kernel(const float* __restrict__ x,
                                                        const float* __restrict__ cb) {
    extern __shared__ float smem[];
    float* As = smem;                    // [2][BK][AS_STRIDE], A duplicated {a,a}
    float* Bs = smem + 2 * AS_BUF;       // [2][BK][BN]

    const int tid = threadIdx.x;
    const int tx = tid & 15;             // owns column pairs {2tx+32j, 2tx+1+32j}
    const int ty = tid >> 4;             // owns rows ty*4 .. ty*4+3

    const int rowTile = blockIdx.x >> 3;
    const int ksplit  = blockIdx.x & 7;
    const int rowBase = rowTile * BM;
    const int b  = rowBase / L_DIM;
    const int l0 = rowBase % L_DIM;
    const float* xb  = x  + (size_t)b * C_DIM * L_DIM + l0;
    const float* cbb = cb + (size_t)ksplit * (K_CB / NSPLIT) * C_DIM;

    // loader mappings
    const int a_c  = tid >> 3;           // 0..31 (c within chunk)
    const int a_m4 = tid & 7;            // float4 index base along m
    const int b_n  = tid & 127;          // codeword within tile
    const int b_cg = tid >> 7;           // 0/1, c-group base

    ULL run[4] = {0ULL, 0ULL, 0ULL, 0ULL};   // running best keys (leader lanes)

    for (int kt = 0; kt < KT_PER_SPLIT; ++kt) {
        const float* cbt = cbb + (size_t)kt * BN * C_DIM;

        ULL acc[4][4];
        #pragma unroll
        for (int i = 0; i < 4; ++i)
            #pragma unroll
            for (int j = 0; j < 4; ++j) acc[i][j] = 0ULL;

        // ---- preload chunk 0 into buffer 0 ----
        {
            #pragma unroll
            for (int it = 0; it < 2; ++it) {
                int m4 = a_m4 + it * 8;
                float4 v = *(const float4*)(xb + (size_t)a_c * L_DIM + m4 * 4);
                float4 w0 = make_float4(v.x, v.x, v.y, v.y);
                float4 w1 = make_float4(v.z, v.z, v.w, v.w);
                *(float4*)&As[a_c * AS_STRIDE + m4 * 8]     = w0;
                *(float4*)&As[a_c * AS_STRIDE + m4 * 8 + 4] = w1;
            }
            const float* brow = cbt + (size_t)b_n * C_DIM;
            #pragma unroll
            for (int it = 0; it < 4; ++it) {
                int cg = b_cg + it * 2;
                float4 v = *(const float4*)(brow + cg * 4);
                Bs[(cg * 4 + 0) * BN + b_n] = v.x;
                Bs[(cg * 4 + 1) * BN + b_n] = v.y;
                Bs[(cg * 4 + 2) * BN + b_n] = v.z;
                Bs[(cg * 4 + 3) * BN + b_n] = v.w;
            }
        }
        __syncthreads();

        int buf = 0;
        for (int s = 0; s < C_DIM / BK; ++s) {
            // ---- issue gmem loads for chunk s+1 (into registers) ----
            float4 av[2], bv[4];
            const bool more = (s < C_DIM / BK - 1);
            if (more) {
                int ck = (s + 1) * BK;
                #pragma unroll
                for (int it = 0; it < 2; ++it) {
                    int m4 = a_m4 + it * 8;
                    av[it] = *(const float4*)(xb + (size_t)(ck + a_c) * L_DIM + m4 * 4);
                }
                const float* brow = cbt + (size_t)b_n * C_DIM + ck;
                #pragma unroll
                for (int it = 0; it < 4; ++it) {
                    int cg = b_cg + it * 2;
                    bv[it] = *(const float4*)(brow + cg * 4);
                }
            }

            // ---- compute on buffer buf ----
            const float* Ab = As + buf * AS_BUF + 8 * ty;
            const float* Bb = Bs + buf * BS_BUF + 2 * tx;
            #pragma unroll
            for (int k = 0; k < BK; ++k) {
                const ULL* ap = (const ULL*)(Ab + k * AS_STRIDE);
                ULL a0 = ap[0], a1 = ap[1], a2 = ap[2], a3 = ap[3];
                const float* br = Bb + k * BN;
                ULL b0 = *(const ULL*)(br);
                ULL b1 = *(const ULL*)(br + 32);
                ULL b2 = *(const ULL*)(br + 64);
                ULL b3 = *(const ULL*)(br + 96);
                acc[0][0] = fma2(a0, b0, acc[0][0]);
                acc[0][1] = fma2(a0, b1, acc[0][1]);
                acc[0][2] = fma2(a0, b2, acc[0][2]);
                acc[0][3] = fma2(a0, b3, acc[0][3]);
                acc[1][0] = fma2(a1, b0, acc[1][0]);
                acc[1][1] = fma2(a1, b1, acc[1][1]);
                acc[1][2] = fma2(a1, b2, acc[1][2]);
                acc[1][3] = fma2(a1, b3, acc[1][3]);
                acc[2][0] = fma2(a2, b0, acc[2][0]);
                acc[2][1] = fma2(a2, b1, acc[2][1]);
                acc[2][2] = fma2(a2, b2, acc[2][2]);
                acc[2][3] = fma2(a2, b3, acc[2][3]);
                acc[3][0] = fma2(a3, b0, acc[3][0]);
                acc[3][1] = fma2(a3, b1, acc[3][1]);
                acc[3][2] = fma2(a3, b2, acc[3][2]);
                acc[3][3] = fma2(a3, b3, acc[3][3]);
            }

            // ---- store staged chunk into the other buffer ----
            if (more) {
                float* Ad = As + (buf ^ 1) * AS_BUF;
                float* Bd = Bs + (buf ^ 1) * BS_BUF;
                #pragma unroll
                for (int it = 0; it < 2; ++it) {
                    int m4 = a_m4 + it * 8;
                    float4 v = av[it];
                    float4 w0 = make_float4(v.x, v.x, v.y, v.y);
                    float4 w1 = make_float4(v.z, v.z, v.w, v.w);
                    *(float4*)&Ad[a_c * AS_STRIDE + m4 * 8]     = w0;
                    *(float4*)&Ad[a_c * AS_STRIDE + m4 * 8 + 4] = w1;
                }
                #pragma unroll
                for (int it = 0; it < 4; ++it) {
                    int cg = b_cg + it * 2;
                    float4 v = bv[it];
                    Bd[(cg * 4 + 0) * BN + b_n] = v.x;
                    Bd[(cg * 4 + 1) * BN + b_n] = v.y;
                    Bd[(cg * 4 + 2) * BN + b_n] = v.z;
                    Bd[(cg * 4 + 3) * BN + b_n] = v.w;
                }
            }
            __syncthreads();
            buf ^= 1;
        }

        // ---- fold this codebook tile into running argmax ----
        const int kBase = ksplit * (K_CB / NSPLIT) + kt * BN;
        float2 cs[4];
        #pragma unroll
        for (int j = 0; j < 4; ++j)
            cs[j] = __ldg((const float2*)&g_csq[kBase + 2 * tx + 32 * j]);

        #pragma unroll
        for (int i = 0; i < 4; ++i) {
            ULL best = 0ULL;
            #pragma unroll
            for (int j = 0; j < 4; ++j) {
                ULL a = acc[i][j];
                float dlo = __uint_as_float((unsigned)(a & 0xffffffffu));
                float dhi = __uint_as_float((unsigned)(a >> 32));
                int n0 = kBase + 2 * tx + 32 * j;
                float s0 = fmaf(-2.0f, dlo, cs[j].x);
                float s1 = fmaf(-2.0f, dhi, cs[j].y);
                best = maxk(best, makeKey(s0, n0));
                best = maxk(best, makeKey(s1, n0 + 1));
            }
            #pragma unroll
            for (int o = 8; o > 0; o >>= 1)
                best = maxk(best, __shfl_xor_sync(0xffffffffu, best, o));
            run[i] = maxk(run[i], best);
        }
    }

    if (tx == 0) {
        #pragma unroll
        for (int i = 0; i < 4; ++i) {
            int row = rowBase + ty * 4 + i;
            g_part[(size_t)row * NSPLIT + ksplit] = run[i];
        }
    }
}

// ---------------- kernel 3: combine split winners -> code --------------------
__global__ void combine_kernel() {
    int i = blockIdx.x * 256 + threadIdx.x;
    if (i >= M_DIM) return;
    const ULL* p = &g_part[(size_t)i * NSPLIT];
    ULL best = p[0];
    #pragma unroll
    for (int s = 1; s < NSPLIT; ++s) best = maxk(best, p[s]);
    g_code[i] = (int)(0xFFFFFFFFu - (unsigned)(best & 0xffffffffu));
}

// ---------------- kernel 4: code -> float output -----------------------------
__global__ void code_cast_kernel(float* __restrict__ out_code) {
    int i = blockIdx.x * 256 + threadIdx.x;
    if (i < M_DIM) out_code[i] = (float)g_code[i];
}

// ---------------- kernel 5: gather emb (B,C,L) + per-block loss partials -----
__global__ void gather_loss_kernel(const float* __restrict__ x,
                                   const float* __restrict__ cb,
                                   float* __restrict__ emb_out) {
    __shared__ float sred[256];
    int idx = blockIdx.x * 256 + threadIdx.x;     // < EMB_N
    int bb  = idx >> 19;                           // / (C*L)
    int rem = idx & ((1 << 19) - 1);
    int c   = rem >> 11;                           // / L
    int l   = rem & (L_DIM - 1);
    int code = g_code[bb * L_DIM + l];
    float v = __ldg(&cb[(size_t)code * C_DIM + c]);
    emb_out[idx] = v;
    float d = x[idx] - v;
    sred[threadIdx.x] = d * d;
    __syncthreads();
    #pragma unroll
    for (int o = 128; o > 0; o >>= 1) {
        if (threadIdx.x < o) sred[threadIdx.x] += sred[threadIdx.x + o];
        __syncthreads();
    }
    if (threadIdx.x == 0) g_partial[blockIdx.x] = sred[0];
}

// ---------------- kernel 6: deterministic final loss reduction ---------------
__global__ void finalize_kernel(float* __restrict__ loss_out) {
    __shared__ float sred[256];
    float s = 0.0f;
    for (int i = threadIdx.x; i < EMB_N / 256; i += 256) s += g_partial[i];
    sred[threadIdx.x] = s;
    __syncthreads();
    #pragma unroll
    for (int o = 128; o > 0; o >>= 1) {
        if (threadIdx.x < o) sred[threadIdx.x] += sred[threadIdx.x + o];
        __syncthreads();
    }
    if (threadIdx.x == 0) loss_out[0] = sred[0] * (1.0f / (float)EMB_N);
}

// ---------------- launch ------------------------------------------------------
extern "C" void kernel_launch(void* const* d_in, const int* in_sizes, int n_in,
                              void* d_out, int out_size) {
    const float* x  = (const float*)d_in[0];   // (8, 256, 2048)
    const float* cb = (const float*)d_in[1];   // (8192, 256)
    float* out = (float*)d_out;

    cudaFuncSetAttribute(argmax_kernel,
                         cudaFuncAttributeMaxDynamicSharedMemorySize, SMEM_BYTES);

    csq_kernel<<<K_CB / 8, 256>>>(cb);
    argmax_kernel<<<(M_DIM / BM) * NSPLIT, 256, SMEM_BYTES>>>(x, cb);
    combine_kernel<<<(M_DIM + 255) / 256, 256>>>();

    const int full = M_DIM + EMB_N + 1;
    if (out_size >= full) {
        // layout: [code (16384), emb (4194304), loss (1)] in return order
        code_cast_kernel<<<(M_DIM + 255) / 256, 256>>>(out);
        gather_loss_kernel<<<EMB_N / 256, 256>>>(x, cb, out + M_DIM);
        finalize_kernel<<<1, 256>>>(out + M_DIM + EMB_N);
    } else if (out_size == EMB_N) {
        gather_loss_kernel<<<EMB_N / 256, 256>>>(x, cb, out);
    } else if (out_size == M_DIM) {
        code_cast_kernel<<<(M_DIM + 255) / 256, 256>>>(out);
    } else {
        gather_loss_kernel<<<EMB_N / 256, 256>>>(x, cb, out);
    }
}